// round 2
// baseline (speedup 1.0000x reference)
#include <cuda_runtime.h>
#include <math.h>

// Problem shapes (fixed by setup_inputs)
#define Bc   2
#define Tc   4096
#define Dc   2048
#define Hc   16
#define Lc   12
#define LHc  192          // L*H
#define Mc   (Bc*Tc)      // 8192 rows
#define D4c  (Dc/4)       // 512 float4 per row

#define EPSV 1.1920929e-07f

// ---------------- scratch (static device globals; no allocation) -------------
__device__ float g_bufA[(size_t)Mc * Dc];   // 67 MB
__device__ float g_bufB[(size_t)Mc * Dc];   // 67 MB
__device__ float g_phi [(size_t)Mc * LHc];  // 6.3 MB

// ---------------- SGEMM: C[m,n] = sum_k A[m,k] * B[n,k]  (A,B row-major, K-contig)
#define BM 128
#define BN 128
#define BK 16
#define TM 8
#define TN 8

__global__ __launch_bounds__(256, 2)
void sgemm_nt(const float* __restrict__ A, const float* __restrict__ B,
              float* __restrict__ C, int M, int N, int K)
{
    __shared__ float As[2][BK][BM];
    __shared__ float Bs[2][BK][BN];

    const int tid = threadIdx.x;
    const int tx  = tid & 15;          // N direction (16)
    const int ty  = tid >> 4;          // M direction (16)
    const int m0  = blockIdx.y * BM;
    const int n0  = blockIdx.x * BN;

    // loader mapping: 512 float4 slots per operand tile; thread handles slot tid and tid+256
    const int lrow = tid >> 2;              // 0..63
    const int lkc  = (tid & 3) << 2;        // 0,4,8,12

    float4 ra[2], rb[2];
    float acc[TM][TN];
#pragma unroll
    for (int i = 0; i < TM; i++)
#pragma unroll
        for (int j = 0; j < TN; j++) acc[i][j] = 0.f;

    const int numT = K / BK;

    // ---- load tile 0 ----
    {
        const int kbase = lkc;
#pragma unroll
        for (int i = 0; i < 2; i++) {
            int rA = m0 + lrow + i * 64;
            ra[i] = (rA < M) ? *(const float4*)(A + (size_t)rA * K + kbase)
                             : make_float4(0.f, 0.f, 0.f, 0.f);
            int rB = n0 + lrow + i * 64;
            rb[i] = (rB < N) ? *(const float4*)(B + (size_t)rB * K + kbase)
                             : make_float4(0.f, 0.f, 0.f, 0.f);
        }
#pragma unroll
        for (int i = 0; i < 2; i++) {
            int r = lrow + i * 64;
            As[0][lkc + 0][r] = ra[i].x; As[0][lkc + 1][r] = ra[i].y;
            As[0][lkc + 2][r] = ra[i].z; As[0][lkc + 3][r] = ra[i].w;
            Bs[0][lkc + 0][r] = rb[i].x; Bs[0][lkc + 1][r] = rb[i].y;
            Bs[0][lkc + 2][r] = rb[i].z; Bs[0][lkc + 3][r] = rb[i].w;
        }
    }
    __syncthreads();

    for (int t = 0; t < numT; t++) {
        const int cur = t & 1;
        const int nxt = cur ^ 1;

        if (t + 1 < numT) {
            const int kbase = (t + 1) * BK + lkc;
#pragma unroll
            for (int i = 0; i < 2; i++) {
                int rA = m0 + lrow + i * 64;
                ra[i] = (rA < M) ? *(const float4*)(A + (size_t)rA * K + kbase)
                                 : make_float4(0.f, 0.f, 0.f, 0.f);
                int rB = n0 + lrow + i * 64;
                rb[i] = (rB < N) ? *(const float4*)(B + (size_t)rB * K + kbase)
                                 : make_float4(0.f, 0.f, 0.f, 0.f);
            }
        }

#pragma unroll
        for (int kk = 0; kk < BK; kk++) {
            float a[TM], b[TN];
            *(float4*)&a[0] = *(const float4*)&As[cur][kk][ty * TM];
            *(float4*)&a[4] = *(const float4*)&As[cur][kk][ty * TM + 4];
            *(float4*)&b[0] = *(const float4*)&Bs[cur][kk][tx * TN];
            *(float4*)&b[4] = *(const float4*)&Bs[cur][kk][tx * TN + 4];
#pragma unroll
            for (int i = 0; i < TM; i++)
#pragma unroll
                for (int j = 0; j < TN; j++)
                    acc[i][j] = fmaf(a[i], b[j], acc[i][j]);
        }

        if (t + 1 < numT) {
#pragma unroll
            for (int i = 0; i < 2; i++) {
                int r = lrow + i * 64;
                As[nxt][lkc + 0][r] = ra[i].x; As[nxt][lkc + 1][r] = ra[i].y;
                As[nxt][lkc + 2][r] = ra[i].z; As[nxt][lkc + 3][r] = ra[i].w;
                Bs[nxt][lkc + 0][r] = rb[i].x; Bs[nxt][lkc + 1][r] = rb[i].y;
                Bs[nxt][lkc + 2][r] = rb[i].z; Bs[nxt][lkc + 3][r] = rb[i].w;
            }
        }
        __syncthreads();
    }

    // ---- store ----
#pragma unroll
    for (int i = 0; i < TM; i++) {
        int m = m0 + ty * TM + i;
        if (m >= M) continue;
#pragma unroll
        for (int j = 0; j < TN; j += 4) {
            int n = n0 + tx * TN + j;
            if (n + 3 < N) {
                *(float4*)(C + (size_t)m * N + n) =
                    make_float4(acc[i][j], acc[i][j + 1], acc[i][j + 2], acc[i][j + 3]);
            } else {
#pragma unroll
                for (int jj = 0; jj < 4; jj++)
                    if (n + jj < N) C[(size_t)m * N + n + jj] = acc[i][j + jj];
            }
        }
    }
}

// ---------------- row RMSNorm (in place), cols multiple of 4 ----------------
__global__ void rmsnorm_rows(float* __restrict__ X, int cols)
{
    const int row = blockIdx.x;
    float* xr = X + (size_t)row * cols;

    float ss = 0.f;
    for (int c = threadIdx.x * 4; c < cols; c += blockDim.x * 4) {
        float4 v = *(const float4*)(xr + c);
        ss += v.x * v.x + v.y * v.y + v.z * v.z + v.w * v.w;
    }
#pragma unroll
    for (int o = 16; o > 0; o >>= 1) ss += __shfl_xor_sync(0xffffffffu, ss, o);

    __shared__ float red[32];
    const int warp = threadIdx.x >> 5, lane = threadIdx.x & 31;
    if (lane == 0) red[warp] = ss;
    __syncthreads();
    if (warp == 0) {
        ss = (lane < (blockDim.x >> 5)) ? red[lane] : 0.f;
#pragma unroll
        for (int o = 16; o > 0; o >>= 1) ss += __shfl_xor_sync(0xffffffffu, ss, o);
        if (lane == 0) red[0] = rsqrtf(ss / (float)cols + EPSV);
    }
    __syncthreads();
    const float r = red[0];

    for (int c = threadIdx.x * 4; c < cols; c += blockDim.x * 4) {
        float4 v = *(const float4*)(xr + c);
        v.x *= r; v.y *= r; v.z *= r; v.w *= r;
        *(float4*)(xr + c) = v;
    }
}

// ---------------- one butterfly level --------------------------------------
// tin/tout: [B*T, D] with D = H*Dh; phi: [B*T, L*H]
__global__ void butterfly(const float* __restrict__ tin, float* __restrict__ tout,
                          const float* __restrict__ phi, int level, int step)
{
    const int g = blockIdx.x * blockDim.x + threadIdx.x;   // float4 index
    const int row = g >> 9;            // g / D4c (D4c = 512)
    const int d4  = g & (D4c - 1);
    const int h   = d4 >> 5;           // (d4*4)/128
    const int t   = row & (Tc - 1);

    const float ph = phi[(size_t)row * LHc + level * Hc + h];
    float s, c;
    sincosf(ph, &s, &c);
    const float k = 0.70710678118654752440f;
    const float cs = c * k, ss = s * k;

    float4 cur = ((const float4*)tin)[g];
    float4 prev = make_float4(0.f, 0.f, 0.f, 0.f);
    if (t >= step) prev = ((const float4*)tin)[g - (size_t)step * D4c];

    float4 o;
    o.x = fmaf(cs, cur.x, ss * prev.x);
    o.y = fmaf(cs, cur.y, ss * prev.y);
    o.z = fmaf(cs, cur.z, ss * prev.z);
    o.w = fmaf(cs, cur.w, ss * prev.w);
    ((float4*)tout)[g] = o;
}

// ---------------- launcher ---------------------------------------------------
extern "C" void kernel_launch(void* const* d_in, const int* in_sizes, int n_in,
                              void* d_out, int out_size)
{
    const float* x     = (const float*)d_in[0];
    const float* W_tok = (const float*)d_in[1];
    const float* W_lvl = (const float*)d_in[2];
    const float* W_out = (const float*)d_in[3];
    float* out = (float*)d_out;

    float *bufA, *bufB, *phi;
    cudaGetSymbolAddress((void**)&bufA, g_bufA);
    cudaGetSymbolAddress((void**)&bufB, g_bufB);
    cudaGetSymbolAddress((void**)&phi,  g_phi);

    const int M = Mc, D = Dc, LH = LHc;

    dim3 gBig(D / BN, M / BM);                 // 16 x 64
    dim3 gLvl((LH + BN - 1) / BN, M / BM);     // 2 x 64

    // theta_raw = x @ W_tok^T ; phi_raw = x @ W_lvl^T
    sgemm_nt<<<gBig, 256>>>(x, W_tok, bufA, M, D, D);
    sgemm_nt<<<gLvl, 256>>>(x, W_lvl, phi,  M, LH, D);

    rmsnorm_rows<<<M, 256>>>(bufA, D);
    rmsnorm_rows<<<M, 256>>>(phi,  LH);

    // 12 butterfly levels, ping-pong between bufA/bufB
    float* pin  = bufA;
    float* pout = bufB;
    const int nThreads = 256;
    const int nBlocks  = (M * D / 4) / nThreads;   // 16384
    for (int l = 0; l < Lc; l++) {
        butterfly<<<nBlocks, nThreads>>>(pin, pout, phi, l, 1 << l);
        float* tmp = pin; pin = pout; pout = tmp;
    }

    // y = theta_final @ W_out^T
    sgemm_nt<<<gBig, 256>>>(pin, W_out, out, M, D, D);
}

// round 5
// speedup vs baseline: 2.9662x; 2.9662x over previous
#include <cuda_runtime.h>
#include <cuda_bf16.h>
#include <cstdint>
#include <math.h>

// ---------------- problem shapes (fixed) ----------------
#define Tc   4096
#define Dc   2048
#define Hc   16
#define Lc   12
#define LHc  192
#define Mc   8192          // B*T
#define KKc  2048          // GEMM K
#define EPSV 1.1920929e-07f
#define INVSQRT2 0.70710678118654752440f

typedef __nv_bfloat16 bf16;

// ---------------- scratch (static device globals; zero-initialized) ----------
__device__ bf16  g_xh [(size_t)Mc * Dc];
__device__ bf16  g_xl [(size_t)Mc * Dc];
__device__ bf16  g_wth[(size_t)Dc * Dc];
__device__ bf16  g_wtl[(size_t)Dc * Dc];
__device__ bf16  g_woh[(size_t)Dc * Dc];
__device__ bf16  g_wol[(size_t)Dc * Dc];
__device__ bf16  g_wlh[(size_t)256 * Dc];   // W_lvl padded 192->256 rows (pad stays 0)
__device__ bf16  g_wll[(size_t)256 * Dc];
__device__ bf16  g_thh[(size_t)Mc * Dc];
__device__ bf16  g_thl[(size_t)Mc * Dc];
__device__ float g_theta [(size_t)Mc * Dc];
__device__ float g_phi   [(size_t)Mc * LHc];
__device__ float g_tscale[(size_t)Mc];
__device__ float2 g_sc   [(size_t)2 * Hc * Lc * Tc];

// ---------------- PTX helpers ----------------
__device__ __forceinline__ uint32_t smem_u32(const void* p) {
    uint32_t a;
    asm("{ .reg .u64 t; cvta.to.shared.u64 t, %1; cvt.u32.u64 %0, t; }" : "=r"(a) : "l"(p));
    return a;
}
__device__ __forceinline__ void cp_async16(uint32_t s, const void* g) {
    asm volatile("cp.async.cg.shared.global [%0], [%1], 16;" :: "r"(s), "l"(g));
}
#define CP_COMMIT() asm volatile("cp.async.commit_group;" ::: "memory")
#define CP_WAIT1()  asm volatile("cp.async.wait_group 1;" ::: "memory")

#define LDSM4(d0,d1,d2,d3,a) \
    asm volatile("ldmatrix.sync.aligned.m8n8.x4.shared.b16 {%0,%1,%2,%3}, [%4];" \
        : "=r"(d0), "=r"(d1), "=r"(d2), "=r"(d3) : "r"(a))

#define MMA_BF16(c, a0,a1,a2,a3, b0,b1) \
    asm volatile("mma.sync.aligned.m16n8k16.row.col.f32.bf16.bf16.f32 " \
        "{%0,%1,%2,%3}, {%4,%5,%6,%7}, {%8,%9}, {%0,%1,%2,%3};" \
        : "+f"((c)[0]), "+f"((c)[1]), "+f"((c)[2]), "+f"((c)[3]) \
        : "r"(a0), "r"(a1), "r"(a2), "r"(a3), "r"(b0), "r"(b1))

// ---------------- bf16 3-term split GEMM on legacy HMMA ----------------
// C[m,n] = sum_k A[m,k]*B[n,k], A ~ Ah+Al, B ~ Bh+Bl (bf16), fp32 accum.
// Block 128x128, 4 warps of 64x64, K chunk 32 (two k16 steps), 3-stage cp.async.
#define RB    80                        // smem row bytes: 32 bf16 (64B) + 16B pad
#define TILE  (128 * RB)                // 10240 B per operand tile
#define STG   (4 * TILE)                // Ah,Al,Bh,Bl per stage = 40960 B
#define NCH   (KKc / 32)                // 64 chunks

__global__ __launch_bounds__(128, 1)
void mma_gemm(const bf16* __restrict__ Ah, const bf16* __restrict__ Al,
              const bf16* __restrict__ Bh, const bf16* __restrict__ Bl,
              float* __restrict__ C, int Nstride, int Nlim)
{
    extern __shared__ char smem[];
    const uint32_t sb = smem_u32(smem);
    const int tid  = threadIdx.x;
    const int wid  = tid >> 5;
    const int lane = tid & 31;
    const int m0 = blockIdx.y * 128;
    const int n0 = blockIdx.x * 128;
    const int wm = (wid & 1) * 64;
    const int wn = (wid >> 1) * 64;

    const int g = lane >> 3, r = lane & 7;
    // fragment base offsets (within a stage); +ks*32 bytes per k16 step
    uint32_t aOff[4], bOff[4];
    #pragma unroll
    for (int mt = 0; mt < 4; mt++)
        aOff[mt] = (uint32_t)((wm + mt * 16 + (g & 1) * 8 + r) * RB + (g >> 1) * 16);
    #pragma unroll
    for (int nt2 = 0; nt2 < 4; nt2++)
        bOff[nt2] = (uint32_t)(2 * TILE + (wn + nt2 * 16 + (g >> 1) * 8 + r) * RB + (g & 1) * 16);

    float acc[4][8][4];
    #pragma unroll
    for (int i = 0; i < 4; i++)
        #pragma unroll
        for (int j = 0; j < 8; j++)
            #pragma unroll
            for (int v = 0; v < 4; v++) acc[i][j][v] = 0.f;

    const bf16* tp[4] = { Ah + (size_t)m0 * KKc, Al + (size_t)m0 * KKc,
                          Bh + (size_t)n0 * KKc, Bl + (size_t)n0 * KKc };

    auto load_stage = [&](int c, int st) {
        const uint32_t base = sb + st * STG;
        #pragma unroll
        for (int t = 0; t < 4; t++) {
            const bf16* src = tp[t] + c * 32;
            #pragma unroll
            for (int i = 0; i < 4; i++) {
                const int idx = tid + i * 128;       // 0..511
                const int row = idx >> 2;
                const int ch  = idx & 3;
                cp_async16(base + t * TILE + row * RB + ch * 16,
                           src + (size_t)row * KKc + ch * 8);
            }
        }
        CP_COMMIT();
    };

    load_stage(0, 0);
    load_stage(1, 1);

    for (int c = 0; c < NCH; c++) {
        CP_WAIT1();
        __syncthreads();
        if (c + 2 < NCH) load_stage(c + 2, (c + 2) % 3);

        const uint32_t stb = sb + (c % 3) * STG;
        #pragma unroll
        for (int ks = 0; ks < 2; ks++) {
            const uint32_t ko = ks * 32;
            uint32_t ah[4][4], xx[4][4];   // xx reused: Al then Bl

            // --- Ah, Bh frags; acc += Ah*Bh
            uint32_t bh[4][4];
            #pragma unroll
            for (int mt = 0; mt < 4; mt++)
                LDSM4(ah[mt][0], ah[mt][1], ah[mt][2], ah[mt][3], stb + aOff[mt] + ko);
            #pragma unroll
            for (int nt2 = 0; nt2 < 4; nt2++)
                LDSM4(bh[nt2][0], bh[nt2][1], bh[nt2][2], bh[nt2][3], stb + bOff[nt2] + ko);
            #pragma unroll
            for (int mt = 0; mt < 4; mt++)
                #pragma unroll
                for (int nt = 0; nt < 8; nt++) {
                    const uint32_t* bb = &bh[nt >> 1][(nt & 1) * 2];
                    MMA_BF16(acc[mt][nt], ah[mt][0], ah[mt][1], ah[mt][2], ah[mt][3], bb[0], bb[1]);
                }

            // --- Al frags; acc += Al*Bh
            #pragma unroll
            for (int mt = 0; mt < 4; mt++)
                LDSM4(xx[mt][0], xx[mt][1], xx[mt][2], xx[mt][3], stb + TILE + aOff[mt] + ko);
            #pragma unroll
            for (int mt = 0; mt < 4; mt++)
                #pragma unroll
                for (int nt = 0; nt < 8; nt++) {
                    const uint32_t* bb = &bh[nt >> 1][(nt & 1) * 2];
                    MMA_BF16(acc[mt][nt], xx[mt][0], xx[mt][1], xx[mt][2], xx[mt][3], bb[0], bb[1]);
                }

            // --- Bl frags; acc += Ah*Bl
            #pragma unroll
            for (int nt2 = 0; nt2 < 4; nt2++)
                LDSM4(xx[nt2][0], xx[nt2][1], xx[nt2][2], xx[nt2][3], stb + TILE + bOff[nt2] + ko);
            #pragma unroll
            for (int mt = 0; mt < 4; mt++)
                #pragma unroll
                for (int nt = 0; nt < 8; nt++) {
                    const uint32_t* bb = &xx[nt >> 1][(nt & 1) * 2];
                    MMA_BF16(acc[mt][nt], ah[mt][0], ah[mt][1], ah[mt][2], ah[mt][3], bb[0], bb[1]);
                }
        }
    }

    // epilogue
    #pragma unroll
    for (int mt = 0; mt < 4; mt++) {
        const int m = m0 + wm + mt * 16 + (lane >> 2);
        #pragma unroll
        for (int nt = 0; nt < 8; nt++) {
            const int n = n0 + wn + nt * 8 + (lane & 3) * 2;
            if (n < Nlim) {
                *(float2*)(C + (size_t)m * Nstride + n) =
                    make_float2(acc[mt][nt][0], acc[mt][nt][1]);
                *(float2*)(C + (size_t)(m + 8) * Nstride + n) =
                    make_float2(acc[mt][nt][2], acc[mt][nt][3]);
            }
        }
    }
}

// ---------------- fp32 -> bf16 hi/lo split ----------------
__global__ void split_bf16(const float4* __restrict__ src,
                           uint2* __restrict__ H, uint2* __restrict__ L, int n4)
{
    int i = blockIdx.x * blockDim.x + threadIdx.x;
    if (i >= n4) return;
    float4 v = src[i];
    bf16 h0 = __float2bfloat16(v.x), h1 = __float2bfloat16(v.y);
    bf16 h2 = __float2bfloat16(v.z), h3 = __float2bfloat16(v.w);
    bf16 l0 = __float2bfloat16(v.x - __bfloat162float(h0));
    bf16 l1 = __float2bfloat16(v.y - __bfloat162float(h1));
    bf16 l2 = __float2bfloat16(v.z - __bfloat162float(h2));
    bf16 l3 = __float2bfloat16(v.w - __bfloat162float(h3));
    __nv_bfloat162 ha = {h0, h1}, hb = {h2, h3}, la = {l0, l1}, lb = {l2, l3};
    H[i] = make_uint2(*(uint32_t*)&ha, *(uint32_t*)&hb);
    L[i] = make_uint2(*(uint32_t*)&la, *(uint32_t*)&lb);
}

// ---------------- theta RMS scale (per-row rsqrt only) ----------------
__global__ void rms_scale(const float* __restrict__ X, float* __restrict__ scale, int cols)
{
    const int row = blockIdx.x;
    const float* xr = X + (size_t)row * cols;
    float ss = 0.f;
    for (int c = threadIdx.x * 4; c < cols; c += blockDim.x * 4) {
        float4 v = *(const float4*)(xr + c);
        ss += v.x * v.x + v.y * v.y + v.z * v.z + v.w * v.w;
    }
    #pragma unroll
    for (int o = 16; o > 0; o >>= 1) ss += __shfl_xor_sync(0xffffffffu, ss, o);
    __shared__ float red[32];
    const int warp = threadIdx.x >> 5, lane = threadIdx.x & 31;
    if (lane == 0) red[warp] = ss;
    __syncthreads();
    if (warp == 0) {
        ss = (lane < (blockDim.x >> 5)) ? red[lane] : 0.f;
        #pragma unroll
        for (int o = 16; o > 0; o >>= 1) ss += __shfl_xor_sync(0xffffffffu, ss, o);
        if (lane == 0) scale[row] = rsqrtf(ss / (float)cols + EPSV);
    }
}

// ---------------- fused RMSNorm(phi) + sincos transpose ----------------
// one block per (b,t) row of 192; writes sc[((b*16+h)*12+l)*4096 + t]
__global__ __launch_bounds__(192)
void phi_rms_sincos(const float* __restrict__ phi, float2* __restrict__ sc)
{
    const int row = blockIdx.x;            // b*4096 + t
    const int t   = row & (Tc - 1);
    const int b   = row >> 12;
    const int j   = threadIdx.x;           // 0..191
    const float v = phi[(size_t)row * LHc + j];

    float ss = v * v;
    #pragma unroll
    for (int o = 16; o > 0; o >>= 1) ss += __shfl_xor_sync(0xffffffffu, ss, o);
    __shared__ float red[6];
    const int warp = j >> 5, lane = j & 31;
    if (lane == 0) red[warp] = ss;
    __syncthreads();
    float tot = red[0] + red[1] + red[2] + red[3] + red[4] + red[5];
    const float rs = rsqrtf(tot / (float)LHc + EPSV);

    const float p = v * rs;
    float s, c;
    sincosf(p, &s, &c);
    const int l = j >> 4, h = j & 15;
    sc[((size_t)(b * Hc + h) * Lc + l) * Tc + t] = make_float2(c * INVSQRT2, s * INVSQRT2);
}

// ---------------- fused 12-level butterfly -> bf16 hi/lo ----------------
__global__ __launch_bounds__(512, 1)
void butterfly_fused(const float* __restrict__ theta, const float* __restrict__ tscale,
                     const float2* __restrict__ sc,
                     bf16* __restrict__ Th, bf16* __restrict__ Tl)
{
    extern __shared__ float th[];   // [4096][9]
    const int ds  = blockIdx.x;     // 0..15
    const int h   = blockIdx.y;     // 0..15
    const int b   = blockIdx.z;     // 0..1
    const int tid = threadIdx.x;
    const int cb  = h * 128 + ds * 8;
    const size_t rowbase = (size_t)b * Tc;

    #pragma unroll
    for (int k = 0; k < 8; k++) {
        const int t = tid + k * 512;
        const float scl = tscale[rowbase + t];
        const float* g = theta + (rowbase + t) * Dc + cb;
        float4 v0 = *(const float4*)g;
        float4 v1 = *(const float4*)(g + 4);
        float* s = &th[t * 9];
        s[0] = v0.x * scl; s[1] = v0.y * scl; s[2] = v0.z * scl; s[3] = v0.w * scl;
        s[4] = v1.x * scl; s[5] = v1.y * scl; s[6] = v1.z * scl; s[7] = v1.w * scl;
    }
    __syncthreads();

    const float2* scb = sc + (size_t)(b * Hc + h) * Lc * Tc;
    for (int l = 0; l < Lc; l++) {
        const int step = 1 << l;
        float2 w[8];
        #pragma unroll
        for (int k = 0; k < 8; k++) w[k] = scb[l * Tc + tid + k * 512];

        #pragma unroll
        for (int jh = 0; jh < 8; jh += 4) {
            float o[8][4];
            #pragma unroll
            for (int k = 0; k < 8; k++) {
                const int t = tid + k * 512;
                #pragma unroll
                for (int j = 0; j < 4; j++) {
                    float cur  = th[t * 9 + jh + j];
                    float prev = (t >= step) ? th[(t - step) * 9 + jh + j] : 0.f;
                    o[k][j] = fmaf(w[k].x, cur, w[k].y * prev);
                }
            }
            __syncthreads();
            #pragma unroll
            for (int k = 0; k < 8; k++) {
                const int t = tid + k * 512;
                #pragma unroll
                for (int j = 0; j < 4; j++) th[t * 9 + jh + j] = o[k][j];
            }
            __syncthreads();
        }
    }

    #pragma unroll
    for (int k = 0; k < 8; k++) {
        const int t = tid + k * 512;
        const float* s = &th[t * 9];
        bf16 hh[8], ll[8];
        #pragma unroll
        for (int j = 0; j < 8; j++) {
            float v = s[j];
            hh[j] = __float2bfloat16(v);
            ll[j] = __float2bfloat16(v - __bfloat162float(hh[j]));
        }
        *(uint4*)(Th + (rowbase + t) * Dc + cb) = *(uint4*)hh;
        *(uint4*)(Tl + (rowbase + t) * Dc + cb) = *(uint4*)ll;
    }
}

// ---------------- launcher ----------------
extern "C" void kernel_launch(void* const* d_in, const int* in_sizes, int n_in,
                              void* d_out, int out_size)
{
    const float* x     = (const float*)d_in[0];
    const float* W_tok = (const float*)d_in[1];
    const float* W_lvl = (const float*)d_in[2];
    const float* W_out = (const float*)d_in[3];
    float* out = (float*)d_out;

    bf16 *xh, *xl, *wth, *wtl, *woh, *wol, *wlh, *wll, *thh, *thl;
    float *theta, *phi, *tscale; float2* sc;
    cudaGetSymbolAddress((void**)&xh,  g_xh);   cudaGetSymbolAddress((void**)&xl,  g_xl);
    cudaGetSymbolAddress((void**)&wth, g_wth);  cudaGetSymbolAddress((void**)&wtl, g_wtl);
    cudaGetSymbolAddress((void**)&woh, g_woh);  cudaGetSymbolAddress((void**)&wol, g_wol);
    cudaGetSymbolAddress((void**)&wlh, g_wlh);  cudaGetSymbolAddress((void**)&wll, g_wll);
    cudaGetSymbolAddress((void**)&thh, g_thh);  cudaGetSymbolAddress((void**)&thl, g_thl);
    cudaGetSymbolAddress((void**)&theta,  g_theta);
    cudaGetSymbolAddress((void**)&phi,    g_phi);
    cudaGetSymbolAddress((void**)&tscale, g_tscale);
    cudaGetSymbolAddress((void**)&sc,     g_sc);

    const int SMEM_GEMM = 3 * STG;              // 122880
    const int SMEM_BFLY = 4096 * 9 * 4;         // 147456
    cudaFuncSetAttribute(mma_gemm, cudaFuncAttributeMaxDynamicSharedMemorySize, SMEM_GEMM);
    cudaFuncSetAttribute(butterfly_fused, cudaFuncAttributeMaxDynamicSharedMemorySize, SMEM_BFLY);

    // 1) split inputs to bf16 hi/lo
    split_bf16<<<(Mc * Dc / 4 + 255) / 256, 256>>>((const float4*)x, (uint2*)xh, (uint2*)xl, Mc * Dc / 4);
    split_bf16<<<(Dc * Dc / 4 + 255) / 256, 256>>>((const float4*)W_tok, (uint2*)wth, (uint2*)wtl, Dc * Dc / 4);
    split_bf16<<<(Dc * Dc / 4 + 255) / 256, 256>>>((const float4*)W_out, (uint2*)woh, (uint2*)wol, Dc * Dc / 4);
    split_bf16<<<(LHc * Dc / 4 + 255) / 256, 256>>>((const float4*)W_lvl, (uint2*)wlh, (uint2*)wll, LHc * Dc / 4);

    // 2) theta_raw = x @ W_tok^T ; phi_raw = x @ W_lvl^T
    mma_gemm<<<dim3(Dc / 128, Mc / 128), 128, SMEM_GEMM>>>(xh, xl, wth, wtl, theta, Dc, Dc);
    mma_gemm<<<dim3(2,        Mc / 128), 128, SMEM_GEMM>>>(xh, xl, wlh, wll, phi, LHc, LHc);

    // 3) norms: theta -> per-row scale; phi -> fused rmsnorm+sincos table
    rms_scale<<<Mc, 256>>>(theta, tscale, Dc);
    phi_rms_sincos<<<Mc, 192>>>(phi, sc);

    // 4) fused butterfly (12 levels), applies tscale, emits bf16 hi/lo
    butterfly_fused<<<dim3(16, Hc, 2), 512, SMEM_BFLY>>>(theta, tscale, sc, thh, thl);

    // 5) y = theta @ W_out^T
    mma_gemm<<<dim3(Dc / 128, Mc / 128), 128, SMEM_GEMM>>>(thh, thl, woh, wol, out, Dc, Dc);
}

// round 6
// speedup vs baseline: 3.1866x; 1.0743x over previous
#include <cuda_runtime.h>
#include <cuda_bf16.h>
#include <cstdint>
#include <math.h>

// ---------------- problem shapes (fixed) ----------------
#define Tc   4096
#define Dc   2048
#define Hc   16
#define Lc   12
#define LHc  192
#define Mc   8192          // B*T
#define KKc  2048          // GEMM K
#define EPSV 1.1920929e-07f
#define INVSQRT2 0.70710678118654752440f

typedef __nv_bfloat16 bf16;

// ---------------- scratch (static device globals; zero-initialized) ----------
__device__ bf16  g_xh [(size_t)Mc * Dc];
__device__ bf16  g_xl [(size_t)Mc * Dc];
__device__ bf16  g_wth[(size_t)Dc * Dc];
__device__ bf16  g_wtl[(size_t)Dc * Dc];
__device__ bf16  g_woh[(size_t)Dc * Dc];
__device__ bf16  g_wol[(size_t)Dc * Dc];
__device__ bf16  g_wlh[(size_t)256 * Dc];   // W_lvl padded 192->256 rows (pad stays 0)
__device__ bf16  g_wll[(size_t)256 * Dc];
__device__ bf16  g_thh[(size_t)Mc * Dc];
__device__ bf16  g_thl[(size_t)Mc * Dc];
__device__ float g_theta [(size_t)Mc * Dc];
__device__ float g_phi   [(size_t)Mc * 256];   // padded cols for tile stores
__device__ float g_tscale[(size_t)Mc];
__device__ float2 g_sc   [(size_t)2 * Hc * Lc * Tc];

// ---------------- PTX helpers ----------------
__device__ __forceinline__ uint32_t smem_u32(const void* p) {
    uint32_t a;
    asm("{ .reg .u64 t; cvta.to.shared.u64 t, %1; cvt.u32.u64 %0, t; }" : "=r"(a) : "l"(p));
    return a;
}
__device__ __forceinline__ void cp_async16(uint32_t s, const void* g) {
    asm volatile("cp.async.cg.shared.global [%0], [%1], 16;" :: "r"(s), "l"(g));
}
#define CP_COMMIT() asm volatile("cp.async.commit_group;" ::: "memory")
#define CP_WAIT1()  asm volatile("cp.async.wait_group 1;" ::: "memory")
#define CP_WAIT0()  asm volatile("cp.async.wait_group 0;" ::: "memory")

#define LDSM4(d0,d1,d2,d3,a) \
    asm volatile("ldmatrix.sync.aligned.m8n8.x4.shared.b16 {%0,%1,%2,%3}, [%4];" \
        : "=r"(d0), "=r"(d1), "=r"(d2), "=r"(d3) : "r"(a))

#define MMA_BF16(c, a0,a1,a2,a3, b0,b1) \
    asm volatile("mma.sync.aligned.m16n8k16.row.col.f32.bf16.bf16.f32 " \
        "{%0,%1,%2,%3}, {%4,%5,%6,%7}, {%8,%9}, {%0,%1,%2,%3};" \
        : "+f"((c)[0]), "+f"((c)[1]), "+f"((c)[2]), "+f"((c)[3]) \
        : "r"(a0), "r"(a1), "r"(a2), "r"(a3), "r"(b0), "r"(b1))

// ---------------- bf16 3-term split GEMM on legacy HMMA ----------------
// C[m,n] = sum_k A[m,k]*B[n,k]; A~Ah+Al, B~Bh+Bl (bf16), fp32 accum.
// Block 128x128, 4 warps of 64x64, K chunk 32 (two k16 steps), 2-stage cp.async,
// 2 CTAs/SM. blockIdx.x >= nxMain selects the secondary (B2,C2) problem.
#define RB    80                        // smem row bytes: 32 bf16 (64B) + 16B pad
#define TILE  (128 * RB)                // 10240 B per operand tile
#define STG   (4 * TILE)                // Ah,Al,Bh,Bl per stage = 40960 B
#define NCH   (KKc / 32)                // 64 chunks

__global__ __launch_bounds__(128, 2)
void mma_gemm(const bf16* __restrict__ Ah, const bf16* __restrict__ Al,
              const bf16* __restrict__ Bh, const bf16* __restrict__ Bl,
              float* __restrict__ C, int NsMain, int nxMain,
              const bf16* __restrict__ Bh2, const bf16* __restrict__ Bl2,
              float* __restrict__ C2)
{
    extern __shared__ char smem[];
    const uint32_t sb = smem_u32(smem);
    const int tid  = threadIdx.x;
    const int wid  = tid >> 5;
    const int lane = tid & 31;
    const int m0 = blockIdx.y * 128;
    const int wm = (wid & 1) * 64;
    const int wn = (wid >> 1) * 64;

    const bf16* BhS; const bf16* BlS; float* CS; int n0, Ns;
    if ((int)blockIdx.x < nxMain) {
        BhS = Bh; BlS = Bl; CS = C; n0 = blockIdx.x * 128; Ns = NsMain;
    } else {
        BhS = Bh2; BlS = Bl2; CS = C2; n0 = (blockIdx.x - nxMain) * 128; Ns = 256;
    }

    const int g = lane >> 3, r = lane & 7;
    uint32_t aOff[4], bOff[4];
    #pragma unroll
    for (int mt = 0; mt < 4; mt++)
        aOff[mt] = (uint32_t)((wm + mt * 16 + (g & 1) * 8 + r) * RB + (g >> 1) * 16);
    #pragma unroll
    for (int nt2 = 0; nt2 < 4; nt2++)
        bOff[nt2] = (uint32_t)(2 * TILE + (wn + nt2 * 16 + (g >> 1) * 8 + r) * RB + (g & 1) * 16);

    float acc[4][8][4];
    #pragma unroll
    for (int i = 0; i < 4; i++)
        #pragma unroll
        for (int j = 0; j < 8; j++)
            #pragma unroll
            for (int v = 0; v < 4; v++) acc[i][j][v] = 0.f;

    const bf16* tp[4] = { Ah + (size_t)m0 * KKc, Al + (size_t)m0 * KKc,
                          BhS + (size_t)n0 * KKc, BlS + (size_t)n0 * KKc };

    auto load_stage = [&](int c, int st) {
        const uint32_t base = sb + st * STG;
        #pragma unroll
        for (int t = 0; t < 4; t++) {
            const bf16* src = tp[t] + c * 32;
            #pragma unroll
            for (int i = 0; i < 4; i++) {
                const int idx = tid + i * 128;       // 0..511
                const int row = idx >> 2;
                const int ch  = idx & 3;
                cp_async16(base + t * TILE + row * RB + ch * 16,
                           src + (size_t)row * KKc + ch * 8);
            }
        }
        CP_COMMIT();
    };

    load_stage(0, 0);

    for (int c = 0; c < NCH; c++) {
        if (c + 1 < NCH) { load_stage(c + 1, (c + 1) & 1); CP_WAIT1(); }
        else             { CP_WAIT0(); }
        __syncthreads();

        const uint32_t stb = sb + (c & 1) * STG;
        #pragma unroll
        for (int ks = 0; ks < 2; ks++) {
            const uint32_t ko = ks * 32;
            uint32_t ah[4][4], bh[4][4], xx[4][4];

            // Ah, Bh frags; acc += Ah*Bh
            #pragma unroll
            for (int mt = 0; mt < 4; mt++)
                LDSM4(ah[mt][0], ah[mt][1], ah[mt][2], ah[mt][3], stb + aOff[mt] + ko);
            #pragma unroll
            for (int nt2 = 0; nt2 < 4; nt2++)
                LDSM4(bh[nt2][0], bh[nt2][1], bh[nt2][2], bh[nt2][3], stb + bOff[nt2] + ko);
            #pragma unroll
            for (int mt = 0; mt < 4; mt++)
                #pragma unroll
                for (int nt = 0; nt < 8; nt++) {
                    const uint32_t* bb = &bh[nt >> 1][(nt & 1) * 2];
                    MMA_BF16(acc[mt][nt], ah[mt][0], ah[mt][1], ah[mt][2], ah[mt][3], bb[0], bb[1]);
                }

            // Al frags; acc += Al*Bh
            #pragma unroll
            for (int mt = 0; mt < 4; mt++)
                LDSM4(xx[mt][0], xx[mt][1], xx[mt][2], xx[mt][3], stb + TILE + aOff[mt] + ko);
            #pragma unroll
            for (int mt = 0; mt < 4; mt++)
                #pragma unroll
                for (int nt = 0; nt < 8; nt++) {
                    const uint32_t* bb = &bh[nt >> 1][(nt & 1) * 2];
                    MMA_BF16(acc[mt][nt], xx[mt][0], xx[mt][1], xx[mt][2], xx[mt][3], bb[0], bb[1]);
                }

            // Bl frags; acc += Ah*Bl
            #pragma unroll
            for (int nt2 = 0; nt2 < 4; nt2++)
                LDSM4(xx[nt2][0], xx[nt2][1], xx[nt2][2], xx[nt2][3], stb + TILE + bOff[nt2] + ko);
            #pragma unroll
            for (int mt = 0; mt < 4; mt++)
                #pragma unroll
                for (int nt = 0; nt < 8; nt++) {
                    const uint32_t* bb = &xx[nt >> 1][(nt & 1) * 2];
                    MMA_BF16(acc[mt][nt], ah[mt][0], ah[mt][1], ah[mt][2], ah[mt][3], bb[0], bb[1]);
                }
        }
        __syncthreads();
    }

    // epilogue
    #pragma unroll
    for (int mt = 0; mt < 4; mt++) {
        const int m = m0 + wm + mt * 16 + (lane >> 2);
        #pragma unroll
        for (int nt = 0; nt < 8; nt++) {
            const int n = n0 + wn + nt * 8 + (lane & 3) * 2;
            *(float2*)(CS + (size_t)m * Ns + n) =
                make_float2(acc[mt][nt][0], acc[mt][nt][1]);
            *(float2*)(CS + (size_t)(m + 8) * Ns + n) =
                make_float2(acc[mt][nt][2], acc[mt][nt][3]);
        }
    }
}

// ---------------- fp32 -> bf16 hi/lo split ----------------
__global__ void split_bf16(const float4* __restrict__ src,
                           uint2* __restrict__ H, uint2* __restrict__ L, int n4)
{
    int i = blockIdx.x * blockDim.x + threadIdx.x;
    if (i >= n4) return;
    float4 v = src[i];
    bf16 h0 = __float2bfloat16(v.x), h1 = __float2bfloat16(v.y);
    bf16 h2 = __float2bfloat16(v.z), h3 = __float2bfloat16(v.w);
    bf16 l0 = __float2bfloat16(v.x - __bfloat162float(h0));
    bf16 l1 = __float2bfloat16(v.y - __bfloat162float(h1));
    bf16 l2 = __float2bfloat16(v.z - __bfloat162float(h2));
    bf16 l3 = __float2bfloat16(v.w - __bfloat162float(h3));
    __nv_bfloat162 ha = {h0, h1}, hb = {h2, h3}, la = {l0, l1}, lb = {l2, l3};
    H[i] = make_uint2(*(uint32_t*)&ha, *(uint32_t*)&hb);
    L[i] = make_uint2(*(uint32_t*)&la, *(uint32_t*)&lb);
}

// ---------------- theta RMS scale (per-row rsqrt only) ----------------
__global__ void rms_scale(const float* __restrict__ X, float* __restrict__ scale, int cols)
{
    const int row = blockIdx.x;
    const float* xr = X + (size_t)row * cols;
    float ss = 0.f;
    for (int c = threadIdx.x * 4; c < cols; c += blockDim.x * 4) {
        float4 v = *(const float4*)(xr + c);
        ss += v.x * v.x + v.y * v.y + v.z * v.z + v.w * v.w;
    }
    #pragma unroll
    for (int o = 16; o > 0; o >>= 1) ss += __shfl_xor_sync(0xffffffffu, ss, o);
    __shared__ float red[32];
    const int warp = threadIdx.x >> 5, lane = threadIdx.x & 31;
    if (lane == 0) red[warp] = ss;
    __syncthreads();
    if (warp == 0) {
        ss = (lane < (blockDim.x >> 5)) ? red[lane] : 0.f;
        #pragma unroll
        for (int o = 16; o > 0; o >>= 1) ss += __shfl_xor_sync(0xffffffffu, ss, o);
        if (lane == 0) scale[row] = rsqrtf(ss / (float)cols + EPSV);
    }
}

// ---------------- fused RMSNorm(phi) + sincos transpose ----------------
__global__ __launch_bounds__(192)
void phi_rms_sincos(const float* __restrict__ phi, float2* __restrict__ sc)
{
    const int row = blockIdx.x;            // b*4096 + t
    const int t   = row & (Tc - 1);
    const int b   = row >> 12;
    const int j   = threadIdx.x;           // 0..191
    const float v = phi[(size_t)row * 256 + j];   // phi padded to 256 cols

    float ss = v * v;
    #pragma unroll
    for (int o = 16; o > 0; o >>= 1) ss += __shfl_xor_sync(0xffffffffu, ss, o);
    __shared__ float red[6];
    const int warp = j >> 5, lane = j & 31;
    if (lane == 0) red[warp] = ss;
    __syncthreads();
    float tot = red[0] + red[1] + red[2] + red[3] + red[4] + red[5];
    const float rs = rsqrtf(tot / (float)LHc + EPSV);

    const float p = v * rs;
    float s, c;
    sincosf(p, &s, &c);
    const int l = j >> 4, h = j & 15;
    sc[((size_t)(b * Hc + h) * Lc + l) * Tc + t] = make_float2(c * INVSQRT2, s * INVSQRT2);
}

// ---------------- fused 12-level butterfly -> bf16 hi/lo ----------------
__global__ __launch_bounds__(512, 1)
void butterfly_fused(const float* __restrict__ theta, const float* __restrict__ tscale,
                     const float2* __restrict__ sc,
                     bf16* __restrict__ Th, bf16* __restrict__ Tl)
{
    extern __shared__ float th[];   // [4096][9]
    const int ds  = blockIdx.x;     // 0..15
    const int h   = blockIdx.y;     // 0..15
    const int b   = blockIdx.z;     // 0..1
    const int tid = threadIdx.x;
    const int cb  = h * 128 + ds * 8;
    const size_t rowbase = (size_t)b * Tc;

    #pragma unroll
    for (int k = 0; k < 8; k++) {
        const int t = tid + k * 512;
        const float scl = tscale[rowbase + t];
        const float* g = theta + (rowbase + t) * Dc + cb;
        float4 v0 = *(const float4*)g;
        float4 v1 = *(const float4*)(g + 4);
        float* s = &th[t * 9];
        s[0] = v0.x * scl; s[1] = v0.y * scl; s[2] = v0.z * scl; s[3] = v0.w * scl;
        s[4] = v1.x * scl; s[5] = v1.y * scl; s[6] = v1.z * scl; s[7] = v1.w * scl;
    }
    __syncthreads();

    const float2* scb = sc + (size_t)(b * Hc + h) * Lc * Tc;
    for (int l = 0; l < Lc; l++) {
        const int step = 1 << l;
        float2 w[8];
        #pragma unroll
        for (int k = 0; k < 8; k++) w[k] = scb[l * Tc + tid + k * 512];

        #pragma unroll
        for (int jh = 0; jh < 8; jh += 4) {
            float o[8][4];
            #pragma unroll
            for (int k = 0; k < 8; k++) {
                const int t = tid + k * 512;
                #pragma unroll
                for (int j = 0; j < 4; j++) {
                    float cur  = th[t * 9 + jh + j];
                    float prev = (t >= step) ? th[(t - step) * 9 + jh + j] : 0.f;
                    o[k][j] = fmaf(w[k].x, cur, w[k].y * prev);
                }
            }
            __syncthreads();
            #pragma unroll
            for (int k = 0; k < 8; k++) {
                const int t = tid + k * 512;
                #pragma unroll
                for (int j = 0; j < 4; j++) th[t * 9 + jh + j] = o[k][j];
            }
            __syncthreads();
        }
    }

    #pragma unroll
    for (int k = 0; k < 8; k++) {
        const int t = tid + k * 512;
        const float* s = &th[t * 9];
        bf16 hh[8], ll[8];
        #pragma unroll
        for (int j = 0; j < 8; j++) {
            float v = s[j];
            hh[j] = __float2bfloat16(v);
            ll[j] = __float2bfloat16(v - __bfloat162float(hh[j]));
        }
        *(uint4*)(Th + (rowbase + t) * Dc + cb) = *(uint4*)hh;
        *(uint4*)(Tl + (rowbase + t) * Dc + cb) = *(uint4*)ll;
    }
}

// ---------------- launcher ----------------
extern "C" void kernel_launch(void* const* d_in, const int* in_sizes, int n_in,
                              void* d_out, int out_size)
{
    const float* x     = (const float*)d_in[0];
    const float* W_tok = (const float*)d_in[1];
    const float* W_lvl = (const float*)d_in[2];
    const float* W_out = (const float*)d_in[3];
    float* out = (float*)d_out;

    bf16 *xh, *xl, *wth, *wtl, *woh, *wol, *wlh, *wll, *thh, *thl;
    float *theta, *phi, *tscale; float2* sc;
    cudaGetSymbolAddress((void**)&xh,  g_xh);   cudaGetSymbolAddress((void**)&xl,  g_xl);
    cudaGetSymbolAddress((void**)&wth, g_wth);  cudaGetSymbolAddress((void**)&wtl, g_wtl);
    cudaGetSymbolAddress((void**)&woh, g_woh);  cudaGetSymbolAddress((void**)&wol, g_wol);
    cudaGetSymbolAddress((void**)&wlh, g_wlh);  cudaGetSymbolAddress((void**)&wll, g_wll);
    cudaGetSymbolAddress((void**)&thh, g_thh);  cudaGetSymbolAddress((void**)&thl, g_thl);
    cudaGetSymbolAddress((void**)&theta,  g_theta);
    cudaGetSymbolAddress((void**)&phi,    g_phi);
    cudaGetSymbolAddress((void**)&tscale, g_tscale);
    cudaGetSymbolAddress((void**)&sc,     g_sc);

    const int SMEM_GEMM = 2 * STG;              // 81920
    const int SMEM_BFLY = 4096 * 9 * 4;         // 147456
    cudaFuncSetAttribute(mma_gemm, cudaFuncAttributeMaxDynamicSharedMemorySize, SMEM_GEMM);
    cudaFuncSetAttribute(butterfly_fused, cudaFuncAttributeMaxDynamicSharedMemorySize, SMEM_BFLY);

    // 1) split inputs to bf16 hi/lo
    split_bf16<<<(Mc * Dc / 4 + 255) / 256, 256>>>((const float4*)x, (uint2*)xh, (uint2*)xl, Mc * Dc / 4);
    split_bf16<<<(Dc * Dc / 4 + 255) / 256, 256>>>((const float4*)W_tok, (uint2*)wth, (uint2*)wtl, Dc * Dc / 4);
    split_bf16<<<(Dc * Dc / 4 + 255) / 256, 256>>>((const float4*)W_out, (uint2*)woh, (uint2*)wol, Dc * Dc / 4);
    split_bf16<<<(LHc * Dc / 4 + 255) / 256, 256>>>((const float4*)W_lvl, (uint2*)wlh, (uint2*)wll, LHc * Dc / 4);

    // 2) merged: theta = x@W_tok^T (x=0..15) and phi = x@W_lvl^T (x=16..17)
    mma_gemm<<<dim3(18, Mc / 128), 128, SMEM_GEMM>>>(xh, xl, wth, wtl, theta, Dc, 16,
                                                     wlh, wll, phi);

    // 3) norms
    rms_scale<<<Mc, 256>>>(theta, tscale, Dc);
    phi_rms_sincos<<<Mc, 192>>>(phi, sc);

    // 4) fused butterfly (12 levels), applies tscale, emits bf16 hi/lo
    butterfly_fused<<<dim3(16, Hc, 2), 512, SMEM_BFLY>>>(theta, tscale, sc, thh, thl);

    // 5) y = theta @ W_out^T
    mma_gemm<<<dim3(16, Mc / 128), 128, SMEM_GEMM>>>(thh, thl, woh, wol, out, Dc, 16,
                                                     nullptr, nullptr, nullptr);
}